// round 7
// baseline (speedup 1.0000x reference)
#include <cuda_runtime.h>
#include <math_constants.h>

#define BN 2
#define NP 65536
#define MR 128
#define NS 6
#define KK 2048
#define NBS (BN*NS)

#define FT 384          // FPS threads (12 warps -> 3 per SMSP)
#define NW (FT/32)      // 12 warps
#define MAXP 8          // max candidate pairs per thread
#define CAP (FT*2*MAXP) // 6144 candidates
#define SMEM_FPS (4*CAP*4)   // sx, sy, sz, sw

typedef unsigned long long u64;
__device__ __forceinline__ u64 f2pack(float lo, float hi) {
    u64 r; asm("mov.b64 %0,{%1,%2};" : "=l"(r) : "f"(lo), "f"(hi)); return r;
}
__device__ __forceinline__ void f2unpack(u64 v, float& lo, float& hi) {
    asm("mov.b64 {%0,%1},%2;" : "=f"(lo), "=f"(hi) : "l"(v));
}
__device__ __forceinline__ u64 add2(u64 a, u64 b) {
    u64 r; asm("add.rn.f32x2 %0,%1,%2;" : "=l"(r) : "l"(a), "l"(b)); return r;
}
__device__ __forceinline__ u64 mul2(u64 a, u64 b) {
    u64 r; asm("mul.rn.f32x2 %0,%1,%2;" : "=l"(r) : "l"(a), "l"(b)); return r;
}

// ---- scratch (__device__ globals: allocation-free) ----
__device__ float4        g_comp[NBS][NP];   // compacted candidates (x,y,z, orig idx bits)
__device__ float         g_dmin[NBS][NP];   // FPS fallback dmin (cnt > CAP only)
__device__ unsigned char g_sec [BN][NP];    // sector code 0..6, 255 = invalid
__device__ int g_cnt[BN][7];                // per-sector counts; [6] = valid-but-sector-6
__device__ int g_buf[BN][KK];

// ---- classify: branchless d2 argmin + single deferred sqrt; exact cleanup on near-tie ----
__global__ void __launch_bounds__(256) k_classify(const float* __restrict__ points,
                                                  const float* __restrict__ rois) {
    __shared__ float4 sroi[MR];  // cx, cy, cz(adjusted), thr = maxdim + 1.6
    int b = blockIdx.y;
    int tid = threadIdx.x;
    if (tid < MR) {
        const float* r = rois + (b * MR + tid) * 7;
        float cx = r[0], cy = r[1], cz = r[2];
        float dx = r[3], dy = r[4], dz = r[5];
        cz = __fadd_rn(cz, __fmul_rn(dz, 0.5f));
        float hx = __fmul_rn(dx, 0.5f), hy = __fmul_rn(dy, 0.5f), hz = __fmul_rn(dz, 0.5f);
        float md = __fsqrt_rn(__fadd_rn(__fadd_rn(__fmul_rn(hx, hx), __fmul_rn(hy, hy)),
                                        __fmul_rn(hz, hz)));
        sroi[tid] = make_float4(cx, cy, cz, __fadd_rn(md, 1.6f));
    }
    __syncthreads();

    int i = blockIdx.x * blockDim.x + tid;
    const float* p = points + ((size_t)b * NP + i) * 3;
    float px = p[0], py = p[1], pz = p[2];

    float m1 = CUDART_INF_F, m2 = CUDART_INF_F;
    int bi = 0;
    #pragma unroll 4
    for (int m = 0; m < MR; m++) {
        float4 c = sroi[m];
        float ax = __fsub_rn(px, c.x);
        float ay = __fsub_rn(py, c.y);
        float az = __fsub_rn(pz, c.z);
        float d2 = __fadd_rn(__fadd_rn(__fmul_rn(ax, ax), __fmul_rn(ay, ay)),
                             __fmul_rn(az, az));
        float mx = fmaxf(d2, m1);
        m2 = fminf(m2, mx);             // runner-up value
        if (d2 < m1) { m1 = d2; bi = m; }  // strict <: first-index tie-break
    }
    float s1 = __fsqrt_rn(m1);
    // d2-argmin == sqrt-argmin unless two d2 round to the same sqrt; detect & redo exactly.
    if (__fsqrt_rn(m2) == s1) {
        float bsv = CUDART_INF_F; int bi2 = 0;
        for (int m = 0; m < MR; m++) {
            float4 c = sroi[m];
            float ax = __fsub_rn(px, c.x);
            float ay = __fsub_rn(py, c.y);
            float az = __fsub_rn(pz, c.z);
            float d2 = __fadd_rn(__fadd_rn(__fmul_rn(ax, ax), __fmul_rn(ay, ay)),
                                 __fmul_rn(az, az));
            float sd = __fsqrt_rn(d2);
            if (sd < bsv) { bsv = sd; bi2 = m; }
        }
        s1 = bsv; bi = bi2;
    }
    bool valid = s1 < sroi[bi].w;

    float ang = __fadd_rn(atan2f(py, px), 3.14159265358979323846f);
    float fs  = floorf(__fdiv_rn(ang, 1.04719755119659774615f));
    fs = fminf(fmaxf(fs, 0.0f), 6.0f);
    int s = (int)fs;

    g_sec[b][i] = valid ? (unsigned char)s : (unsigned char)255;
}

// ---- compact: 1 warp per contiguous 2048-pt range, 2 barriers total ----
__global__ void __launch_bounds__(1024) k_compact(const float* __restrict__ points) {
    int bs = blockIdx.x;
    int tid = threadIdx.x, lane = tid & 31, wid = tid >> 5;
    __shared__ int wcnt[32];
    __shared__ int woff[32];

    if (bs >= NBS) {  // count-only: sector 6 of batch b
        int b = bs - NBS;
        const unsigned char* sec = g_sec[b];
        int c = 0;
        for (int i = tid; i < NP; i += 1024)
            c += (sec[i] == (unsigned char)6);
        c = __reduce_add_sync(0xffffffffu, c);
        if (lane == 0) wcnt[wid] = c;
        __syncthreads();
        if (tid == 0) {
            int t = 0;
            for (int w = 0; w < 32; w++) t += wcnt[w];
            g_cnt[b][6] = t;
        }
        return;
    }

    int b = bs / NS, s = bs - b * NS;
    const unsigned char* sec = g_sec[b];
    const float* pts = points + (size_t)b * NP * 3;
    const int R = NP / 32;           // 2048 points per warp, contiguous (stable order)
    int r0 = wid * R;

    int c = 0;
    for (int t = 0; t < R / 32; t++) {
        int i = r0 + t * 32 + lane;
        unsigned m = __ballot_sync(0xffffffffu, sec[i] == (unsigned char)s);
        c += __popc(m);
    }
    if (lane == 0) wcnt[wid] = c;
    __syncthreads();
    if (wid == 0) {
        int v = wcnt[lane];
        int orig = v;
        #pragma unroll
        for (int o = 1; o < 32; o <<= 1) {
            int u = __shfl_up_sync(0xffffffffu, v, o);
            if (lane >= o) v += u;
        }
        woff[lane] = v - orig;
        if (lane == 31) g_cnt[b][s] = v;
    }
    __syncthreads();
    int pos = woff[wid];
    float4* __restrict__ comp = g_comp[bs];
    for (int t = 0; t < R / 32; t++) {
        int i = r0 + t * 32 + lane;
        bool f = (sec[i] == (unsigned char)s);
        unsigned m = __ballot_sync(0xffffffffu, f);
        if (f) {
            float4 q;
            q.x = pts[3 * i];
            q.y = pts[3 * i + 1];
            q.z = pts[3 * i + 2];
            q.w = __int_as_float(i);
            comp[pos + __popc(m & ((1u << lane) - 1u))] = q;
        }
        pos += __popc(m);
    }
}

// budget for (b, s): returns nk and off (prefix of earlier sectors' nk)
__device__ __forceinline__ void budget(int b, int s, int& nk, int& off) {
    int cs[NS];
    int total = g_cnt[b][6];
    #pragma unroll
    for (int t = 0; t < NS; t++) { cs[t] = g_cnt[b][t]; total += cs[t]; }
    if (total < 1) total = 1;
    off = 0; nk = 0;
    #pragma unroll
    for (int t = 0; t < NS; t++) {
        float q = __fdiv_rn(__fmul_rn((float)cs[t], 2048.0f), (float)total);
        int n = (int)ceilf(q);
        if (n > cs[t]) n = cs[t];
        if (t < s) off += n;
        if (t == s) nk = n;
    }
}

// ---- FPS v7 inner loop: value-only hot loop, keyed atomicMax, ONE barrier/iter ----
template<int P>
__device__ __forceinline__ void fps_loop(
    int b, int off, int nEff, int cnt,
    const float* __restrict__ sx, const float* __restrict__ sy,
    const float* __restrict__ sz, const float* __restrict__ sw,
    u64* sKey)
{
    int tid = threadIdx.x;
    u64 pxp[P], pyp[P], pzp[P];
    float dm[2 * P];
    #pragma unroll
    for (int p = 0; p < P; p++) {
        int i0 = (2 * p) * FT + tid, i1 = (2 * p + 1) * FT + tid;
        float x0 = 0, y0 = 0, z0 = 0, x1 = 0, y1 = 0, z1 = 0;
        if (i0 < cnt) { x0 = sx[i0]; y0 = sy[i0]; z0 = sz[i0];
                        dm[2 * p] = CUDART_INF_F; }
        else dm[2 * p] = -CUDART_INF_F;
        if (i1 < cnt) { x1 = sx[i1]; y1 = sy[i1]; z1 = sz[i1];
                        dm[2 * p + 1] = CUDART_INF_F; }
        else dm[2 * p + 1] = -CUDART_INF_F;
        pxp[p] = f2pack(x0, x1); pyp[p] = f2pack(y0, y1); pzp[p] = f2pack(z0, z1);
    }
    float lx = sx[0], ly = sy[0], lz = sz[0];

    for (int j = 1; j < nEff; j++) {
        u64 nlx = f2pack(-lx, -lx), nly = f2pack(-ly, -ly), nlz = f2pack(-lz, -lz);
        float vmax = -CUDART_INF_F;
        #pragma unroll
        for (int p = 0; p < P; p++) {
            u64 ax = add2(pxp[p], nlx);
            u64 ay = add2(pyp[p], nly);
            u64 az = add2(pzp[p], nlz);
            u64 d2p = add2(add2(mul2(ax, ax), mul2(ay, ay)), mul2(az, az));
            float d2a, d2b; f2unpack(d2p, d2a, d2b);
            float a = fminf(dm[2 * p], d2a);          // -inf slots stay -inf
            float c = fminf(dm[2 * p + 1], d2b);
            dm[2 * p] = a; dm[2 * p + 1] = c;
            vmax = fmaxf(vmax, fmaxf(a, c));
        }
        // warp filter (~1 lane/warp), then keyed atomicMax: value desc, slot asc
        unsigned vb = (vmax < 0.0f) ? 0u : __float_as_uint(vmax);
        unsigned wm = __reduce_max_sync(0xffffffffu, vb);
        if (vb == wm && vmax >= 0.0f) {
            int cand = 0x7fffffff;
            #pragma unroll
            for (int k = 2 * P - 1; k >= 0; k--)      // ends at lowest matching slot
                if (dm[k] == vmax) cand = k * FT + tid;
            u64 key = ((u64)vb << 32) | (u64)(0x7fffffffu - (unsigned)cand);
            atomicMax(&sKey[j & 3], key);
        }
        __syncthreads();                               // the only barrier per pick
        if (tid == 0) sKey[(j + 2) & 3] = 0;           // ring reset: used at j+4, safe
        u64 kk = sKey[j & 3];
        int slot = (int)(0x7fffffffu - (unsigned)(kk & 0xffffffffu));
        lx = sx[slot]; ly = sy[slot]; lz = sz[slot];
        if (tid == 0) g_buf[b][off + j] = __float_as_int(sw[slot]);
    }
}

__global__ void __launch_bounds__(FT) k_fps7() {
    extern __shared__ float smf[];
    float* sx = smf;
    float* sy = sx + CAP;
    float* sz = sy + CAP;
    float* sw = sz + CAP;
    __shared__ __align__(8) u64 sKey[4];
    __shared__ unsigned fV[2][NW], fI[2][NW];   // fallback reduction scratch

    int bs = blockIdx.x;
    int b = bs / NS, s = bs - b * NS;
    int cnt = g_cnt[b][s];
    int nk, off;
    budget(b, s, nk, off);
    if (nk <= 0 || off >= KK) return;
    int nEff = nk;
    if (off + nEff > KK) nEff = KK - off;

    int tid = threadIdx.x, lane = tid & 31, wid = tid >> 5;
    const float4* __restrict__ comp = g_comp[bs];

    if (cnt <= CAP) {
        for (int i = tid; i < cnt; i += FT) {
            float4 q = comp[i];
            sx[i] = q.x; sy[i] = q.y; sz[i] = q.z; sw[i] = q.w;
        }
        if (tid < 4) sKey[tid] = 0;
        __syncthreads();
        if (tid == 0) g_buf[b][off] = __float_as_int(sw[0]);
        int pairs = (cnt + 2 * FT - 1) / (2 * FT);
        switch (pairs) {
            case 1: fps_loop<1>(b, off, nEff, cnt, sx, sy, sz, sw, sKey); break;
            case 2: fps_loop<2>(b, off, nEff, cnt, sx, sy, sz, sw, sKey); break;
            case 3: fps_loop<3>(b, off, nEff, cnt, sx, sy, sz, sw, sKey); break;
            case 4: fps_loop<4>(b, off, nEff, cnt, sx, sy, sz, sw, sKey); break;
            case 5: fps_loop<5>(b, off, nEff, cnt, sx, sy, sz, sw, sKey); break;
            case 6: fps_loop<6>(b, off, nEff, cnt, sx, sy, sz, sw, sKey); break;
            case 7: fps_loop<7>(b, off, nEff, cnt, sx, sy, sz, sw, sKey); break;
            default: fps_loop<8>(b, off, nEff, cnt, sx, sy, sz, sw, sKey); break;
        }
    } else {
        // ---- gmem fallback (rare; correctness net) ----
        float* __restrict__ D = g_dmin[bs];
        float4 p0 = comp[0];
        if (tid == 0) g_buf[b][off] = __float_as_int(p0.w);
        float lx = p0.x, ly = p0.y, lz = p0.z;
        for (int j = 1; j < nEff; j++) {
            float vmax = -CUDART_INF_F;
            unsigned vidx = 0x7fffffffu;
            for (int i = tid; i < cnt; i += FT) {
                float4 p = comp[i];
                float ax = __fsub_rn(p.x, lx), ay = __fsub_rn(p.y, ly), az = __fsub_rn(p.z, lz);
                float d2 = __fadd_rn(__fadd_rn(__fmul_rn(ax, ax), __fmul_rn(ay, ay)),
                                     __fmul_rn(az, az));
                float dmn = (j == 1) ? d2 : fminf(D[i], d2);
                D[i] = dmn;
                if (dmn > vmax) { vmax = dmn; vidx = (unsigned)i; }
            }
            unsigned vb = (vmax < 0.0f) ? 0u : __float_as_uint(vmax);
            unsigned wm = __reduce_max_sync(0xffffffffu, vb);
            unsigned ci = (vb == wm) ? vidx : 0xffffffffu;
            unsigned wi = __reduce_min_sync(0xffffffffu, ci);
            int par = j & 1;
            if (lane == 0) { fV[par][wid] = wm; fI[par][wid] = wi; }
            __syncthreads();
            unsigned bv = fV[par][0], bp = fI[par][0];
            #pragma unroll
            for (int w2 = 1; w2 < NW; w2++) {
                unsigned v = fV[par][w2], i2 = fI[par][w2];
                if (v > bv || (v == bv && i2 < bp)) { bv = v; bp = i2; }
            }
            float4 pw = comp[bp];
            lx = pw.x; ly = pw.y; lz = pw.z;
            if (tid == 0) g_buf[b][off + j] = __float_as_int(pw.w);
        }
    }
}

// ---- gather output ----
__global__ void k_out(const float* __restrict__ points, float* __restrict__ out) {
    int t = blockIdx.x * blockDim.x + threadIdx.x;
    if (t >= BN * KK) return;
    int b = t / KK, i = t - b * KK;
    int cs[NS];
    int total = g_cnt[b][6];
    #pragma unroll
    for (int s = 0; s < NS; s++) { cs[s] = g_cnt[b][s]; total += cs[s]; }
    if (total < 1) total = 1;
    int st = 0;
    #pragma unroll
    for (int s = 0; s < NS; s++) {
        float q = __fdiv_rn(__fmul_rn((float)cs[s], 2048.0f), (float)total);
        int n = (int)ceilf(q);
        if (n > cs[s]) n = cs[s];
        st += n;
    }
    if (st < 1) st = 1;
    int src = g_buf[b][i % st];
    const float* p = points + ((size_t)b * NP + src) * 3;
    out[3 * t + 0] = p[0];
    out[3 * t + 1] = p[1];
    out[3 * t + 2] = p[2];
}

extern "C" void kernel_launch(void* const* d_in, const int* in_sizes, int n_in,
                              void* d_out, int out_size) {
    const float* points = (const float*)d_in[0];  // [2,65536,3] f32
    const float* rois   = (const float*)d_in[1];  // [2,128,7]  f32
    float* out = (float*)d_out;                   // [2,2048,3] f32

    cudaFuncSetAttribute(k_fps7, cudaFuncAttributeMaxDynamicSharedMemorySize, SMEM_FPS);

    dim3 gc(NP / 256, BN);
    k_classify<<<gc, 256>>>(points, rois);
    k_compact<<<NBS + BN, 1024>>>(points);
    k_fps7<<<NBS, FT, SMEM_FPS>>>();
    k_out<<<(BN * KK + 255) / 256, 256>>>(points, out);
}

// round 8
// speedup vs baseline: 1.3757x; 1.3757x over previous
#include <cuda_runtime.h>
#include <math_constants.h>

#define BN 2
#define NP 65536
#define MR 128
#define NS 6
#define KK 2048
#define NBS (BN*NS)

#define FT 256          // FPS threads (8 warps -> 2 per SMSP)
#define NW (FT/32)      // 8 warps
#define MAXP 12         // max candidate pairs per thread
#define CAP (FT*2*MAXP) // 6144 candidates
#define SMEM_FPS (CAP*16)    // float4 sP[CAP]

typedef unsigned long long u64;
__device__ __forceinline__ u64 f2pack(float lo, float hi) {
    u64 r; asm("mov.b64 %0,{%1,%2};" : "=l"(r) : "f"(lo), "f"(hi)); return r;
}
__device__ __forceinline__ void f2unpack(u64 v, float& lo, float& hi) {
    asm("mov.b64 {%0,%1},%2;" : "=f"(lo), "=f"(hi) : "l"(v));
}
__device__ __forceinline__ u64 add2(u64 a, u64 b) {
    u64 r; asm("add.rn.f32x2 %0,%1,%2;" : "=l"(r) : "l"(a), "l"(b)); return r;
}
__device__ __forceinline__ u64 mul2(u64 a, u64 b) {
    u64 r; asm("mul.rn.f32x2 %0,%1,%2;" : "=l"(r) : "l"(a), "l"(b)); return r;
}

// ---- scratch (__device__ globals: allocation-free) ----
__device__ float4        g_comp[NBS][NP];   // compacted candidates (x,y,z, orig idx bits)
__device__ float         g_dmin[NBS][NP];   // FPS fallback dmin (cnt > CAP only)
__device__ unsigned char g_sec [BN][NP];    // sector code 0..6, 255 = invalid
__device__ int g_cnt[BN][7];                // per-sector counts; [6] = valid-but-sector-6
__device__ int g_buf[BN][KK];

// ---- classify: branchless d2 argmin + single deferred sqrt; exact cleanup on near-tie ----
__global__ void __launch_bounds__(256) k_classify(const float* __restrict__ points,
                                                  const float* __restrict__ rois) {
    __shared__ float4 sroi[MR];  // cx, cy, cz(adjusted), thr = maxdim + 1.6
    int b = blockIdx.y;
    int tid = threadIdx.x;
    if (tid < MR) {
        const float* r = rois + (b * MR + tid) * 7;
        float cx = r[0], cy = r[1], cz = r[2];
        float dx = r[3], dy = r[4], dz = r[5];
        cz = __fadd_rn(cz, __fmul_rn(dz, 0.5f));
        float hx = __fmul_rn(dx, 0.5f), hy = __fmul_rn(dy, 0.5f), hz = __fmul_rn(dz, 0.5f);
        float md = __fsqrt_rn(__fadd_rn(__fadd_rn(__fmul_rn(hx, hx), __fmul_rn(hy, hy)),
                                        __fmul_rn(hz, hz)));
        sroi[tid] = make_float4(cx, cy, cz, __fadd_rn(md, 1.6f));
    }
    __syncthreads();

    int i = blockIdx.x * blockDim.x + tid;
    const float* p = points + ((size_t)b * NP + i) * 3;
    float px = p[0], py = p[1], pz = p[2];

    float m1 = CUDART_INF_F, m2 = CUDART_INF_F;
    int bi = 0;
    #pragma unroll 4
    for (int m = 0; m < MR; m++) {
        float4 c = sroi[m];
        float ax = __fsub_rn(px, c.x);
        float ay = __fsub_rn(py, c.y);
        float az = __fsub_rn(pz, c.z);
        float d2 = __fadd_rn(__fadd_rn(__fmul_rn(ax, ax), __fmul_rn(ay, ay)),
                             __fmul_rn(az, az));
        float mx = fmaxf(d2, m1);
        m2 = fminf(m2, mx);             // runner-up value
        if (d2 < m1) { m1 = d2; bi = m; }  // strict <: first-index tie-break
    }
    float s1 = __fsqrt_rn(m1);
    // d2-argmin == sqrt-argmin unless two d2 round to the same sqrt; detect & redo exactly.
    if (__fsqrt_rn(m2) == s1) {
        float bsv = CUDART_INF_F; int bi2 = 0;
        for (int m = 0; m < MR; m++) {
            float4 c = sroi[m];
            float ax = __fsub_rn(px, c.x);
            float ay = __fsub_rn(py, c.y);
            float az = __fsub_rn(pz, c.z);
            float d2 = __fadd_rn(__fadd_rn(__fmul_rn(ax, ax), __fmul_rn(ay, ay)),
                                 __fmul_rn(az, az));
            float sd = __fsqrt_rn(d2);
            if (sd < bsv) { bsv = sd; bi2 = m; }
        }
        s1 = bsv; bi = bi2;
    }
    bool valid = s1 < sroi[bi].w;

    float ang = __fadd_rn(atan2f(py, px), 3.14159265358979323846f);
    float fs  = floorf(__fdiv_rn(ang, 1.04719755119659774615f));
    fs = fminf(fmaxf(fs, 0.0f), 6.0f);
    int s = (int)fs;

    g_sec[b][i] = valid ? (unsigned char)s : (unsigned char)255;
}

// ---- compact: 1 warp per contiguous 2048-pt range, 2 barriers total ----
__global__ void __launch_bounds__(1024) k_compact(const float* __restrict__ points) {
    int bs = blockIdx.x;
    int tid = threadIdx.x, lane = tid & 31, wid = tid >> 5;
    __shared__ int wcnt[32];
    __shared__ int woff[32];

    if (bs >= NBS) {  // count-only: sector 6 of batch b
        int b = bs - NBS;
        const unsigned char* sec = g_sec[b];
        int c = 0;
        for (int i = tid; i < NP; i += 1024)
            c += (sec[i] == (unsigned char)6);
        c = __reduce_add_sync(0xffffffffu, c);
        if (lane == 0) wcnt[wid] = c;
        __syncthreads();
        if (tid == 0) {
            int t = 0;
            for (int w = 0; w < 32; w++) t += wcnt[w];
            g_cnt[b][6] = t;
        }
        return;
    }

    int b = bs / NS, s = bs - b * NS;
    const unsigned char* sec = g_sec[b];
    const float* pts = points + (size_t)b * NP * 3;
    const int R = NP / 32;           // 2048 points per warp, contiguous (stable order)
    int r0 = wid * R;

    int c = 0;
    for (int t = 0; t < R / 32; t++) {
        int i = r0 + t * 32 + lane;
        unsigned m = __ballot_sync(0xffffffffu, sec[i] == (unsigned char)s);
        c += __popc(m);
    }
    if (lane == 0) wcnt[wid] = c;
    __syncthreads();
    if (wid == 0) {
        int v = wcnt[lane];
        int orig = v;
        #pragma unroll
        for (int o = 1; o < 32; o <<= 1) {
            int u = __shfl_up_sync(0xffffffffu, v, o);
            if (lane >= o) v += u;
        }
        woff[lane] = v - orig;
        if (lane == 31) g_cnt[b][s] = v;
    }
    __syncthreads();
    int pos = woff[wid];
    float4* __restrict__ comp = g_comp[bs];
    for (int t = 0; t < R / 32; t++) {
        int i = r0 + t * 32 + lane;
        bool f = (sec[i] == (unsigned char)s);
        unsigned m = __ballot_sync(0xffffffffu, f);
        if (f) {
            float4 q;
            q.x = pts[3 * i];
            q.y = pts[3 * i + 1];
            q.z = pts[3 * i + 2];
            q.w = __int_as_float(i);
            comp[pos + __popc(m & ((1u << lane) - 1u))] = q;
        }
        pos += __popc(m);
    }
}

// budget for (b, s): returns nk and off (prefix of earlier sectors' nk)
__device__ __forceinline__ void budget(int b, int s, int& nk, int& off) {
    int cs[NS];
    int total = g_cnt[b][6];
    #pragma unroll
    for (int t = 0; t < NS; t++) { cs[t] = g_cnt[b][t]; total += cs[t]; }
    if (total < 1) total = 1;
    off = 0; nk = 0;
    #pragma unroll
    for (int t = 0; t < NS; t++) {
        float q = __fdiv_rn(__fmul_rn((float)cs[t], 2048.0f), (float)total);
        int n = (int)ceilf(q);
        if (n > cs[t]) n = cs[t];
        if (t < s) off += n;
        if (t == s) nk = n;
    }
}

// ---- FPS v8: R6 topology (value-only loop, lazy index, 2 bars), trimmed tail ----
template<int P>
__device__ __forceinline__ void fps_loop(
    int b, int off, int nEff, int cnt,
    const float4* __restrict__ sP,
    float (*sV)[NW], int* sIdx)
{
    int tid = threadIdx.x, lane = tid & 31, wid = tid >> 5;
    u64 pxp[P], pyp[P], pzp[P];
    float dm[2 * P];
    #pragma unroll
    for (int p = 0; p < P; p++) {
        int i0 = (2 * p) * FT + tid, i1 = (2 * p + 1) * FT + tid;
        float x0 = 0, y0 = 0, z0 = 0, x1 = 0, y1 = 0, z1 = 0;
        if (i0 < cnt) { float4 q = sP[i0]; x0 = q.x; y0 = q.y; z0 = q.z;
                        dm[2 * p] = CUDART_INF_F; }
        else dm[2 * p] = -CUDART_INF_F;
        if (i1 < cnt) { float4 q = sP[i1]; x1 = q.x; y1 = q.y; z1 = q.z;
                        dm[2 * p + 1] = CUDART_INF_F; }
        else dm[2 * p + 1] = -CUDART_INF_F;
        pxp[p] = f2pack(x0, x1); pyp[p] = f2pack(y0, y1); pzp[p] = f2pack(z0, z1);
    }
    float4 pv0 = sP[0];
    float lx = pv0.x, ly = pv0.y, lz = pv0.z;

    for (int j = 1; j < nEff; j++) {
        int par = j & 1;
        u64 nlx = f2pack(-lx, -lx), nly = f2pack(-ly, -ly), nlz = f2pack(-lz, -lz);
        float vmax = -CUDART_INF_F;
        #pragma unroll
        for (int p = 0; p < P; p++) {
            u64 ax = add2(pxp[p], nlx);
            u64 ay = add2(pyp[p], nly);
            u64 az = add2(pzp[p], nlz);
            u64 d2p = add2(add2(mul2(ax, ax), mul2(ay, ay)), mul2(az, az));
            float d2a, d2b; f2unpack(d2p, d2a, d2b);
            float a = fminf(dm[2 * p], d2a);          // -inf slots stay -inf
            float c = fminf(dm[2 * p + 1], d2b);
            dm[2 * p] = a; dm[2 * p + 1] = c;
            vmax = fmaxf(vmax, fmaxf(a, c));
        }
        unsigned vb = (vmax < 0.0f) ? 0u : __float_as_uint(vmax);
        unsigned wm = __reduce_max_sync(0xffffffffu, vb);    // bits order-iso for >= 0
        if (lane == 0) sV[par][wid] = __uint_as_float(wm);
        __syncthreads();
        if (tid == 0) sIdx[par ^ 1] = 0x7fffffff;   // reset other parity (safe window)
        // blockmax: 2 vector LDS + 7 FMNMX, value only
        float4 v0 = *(const float4*)&sV[par][0];
        float4 v1 = *(const float4*)&sV[par][4];
        float bm = fmaxf(fmaxf(fmaxf(v0.x, v0.y), fmaxf(v0.z, v0.w)),
                         fmaxf(fmaxf(v1.x, v1.y), fmaxf(v1.z, v1.w)));
        if (vmax == bm) {                            // ~1 thread; dead threads (-inf) never
            int cand = 0x7fffffff;
            #pragma unroll
            for (int k = 2 * P - 1; k >= 0; k--)     // ends at lowest matching slot
                if (dm[k] == bm) cand = k * FT + tid;
            atomicMin(&sIdx[par], cand);             // lowest global index = exact tie-break
        }
        __syncthreads();
        int widx = sIdx[par];
        float4 pw = sP[widx];                        // single LDS.128 broadcast
        lx = pw.x; ly = pw.y; lz = pw.z;
        if (tid == 0) g_buf[b][off + j] = __float_as_int(pw.w);
    }
}

__global__ void __launch_bounds__(FT) k_fps8() {
    extern __shared__ float4 sP[];                   // [CAP]
    __shared__ __align__(16) float sV[2][NW];
    __shared__ int sIdx[2];
    __shared__ unsigned fV[2][NW], fI[2][NW];        // fallback reduction scratch

    int bs = blockIdx.x;
    int b = bs / NS, s = bs - b * NS;
    int cnt = g_cnt[b][s];
    int nk, off;
    budget(b, s, nk, off);
    if (nk <= 0 || off >= KK) return;
    int nEff = nk;
    if (off + nEff > KK) nEff = KK - off;

    int tid = threadIdx.x, lane = tid & 31, wid = tid >> 5;
    const float4* __restrict__ comp = g_comp[bs];

    if (cnt <= CAP) {
        for (int i = tid; i < cnt; i += FT) sP[i] = comp[i];
        if (tid == 0) { sIdx[0] = 0x7fffffff; sIdx[1] = 0x7fffffff; }
        __syncthreads();
        if (tid == 0) g_buf[b][off] = __float_as_int(sP[0].w);
        int pairs = (cnt + 2 * FT - 1) / (2 * FT);
        switch (pairs) {
            case 1:  fps_loop<1>(b, off, nEff, cnt, sP, sV, sIdx); break;
            case 2:  fps_loop<2>(b, off, nEff, cnt, sP, sV, sIdx); break;
            case 3:  fps_loop<3>(b, off, nEff, cnt, sP, sV, sIdx); break;
            case 4:  fps_loop<4>(b, off, nEff, cnt, sP, sV, sIdx); break;
            case 5:  fps_loop<5>(b, off, nEff, cnt, sP, sV, sIdx); break;
            case 6:  fps_loop<6>(b, off, nEff, cnt, sP, sV, sIdx); break;
            case 7:  fps_loop<7>(b, off, nEff, cnt, sP, sV, sIdx); break;
            case 8:  fps_loop<8>(b, off, nEff, cnt, sP, sV, sIdx); break;
            case 9:  fps_loop<9>(b, off, nEff, cnt, sP, sV, sIdx); break;
            case 10: fps_loop<10>(b, off, nEff, cnt, sP, sV, sIdx); break;
            case 11: fps_loop<11>(b, off, nEff, cnt, sP, sV, sIdx); break;
            default: fps_loop<12>(b, off, nEff, cnt, sP, sV, sIdx); break;
        }
    } else {
        // ---- gmem fallback (rare; correctness net) ----
        float* __restrict__ D = g_dmin[bs];
        float4 p0 = comp[0];
        if (tid == 0) g_buf[b][off] = __float_as_int(p0.w);
        float lx = p0.x, ly = p0.y, lz = p0.z;
        for (int j = 1; j < nEff; j++) {
            float vmax = -CUDART_INF_F;
            unsigned vidx = 0x7fffffffu;
            for (int i = tid; i < cnt; i += FT) {
                float4 p = comp[i];
                float ax = __fsub_rn(p.x, lx), ay = __fsub_rn(p.y, ly), az = __fsub_rn(p.z, lz);
                float d2 = __fadd_rn(__fadd_rn(__fmul_rn(ax, ax), __fmul_rn(ay, ay)),
                                     __fmul_rn(az, az));
                float dmn = (j == 1) ? d2 : fminf(D[i], d2);
                D[i] = dmn;
                if (dmn > vmax) { vmax = dmn; vidx = (unsigned)i; }
            }
            unsigned vb = (vmax < 0.0f) ? 0u : __float_as_uint(vmax);
            unsigned wm = __reduce_max_sync(0xffffffffu, vb);
            unsigned ci = (vb == wm) ? vidx : 0xffffffffu;
            unsigned wi = __reduce_min_sync(0xffffffffu, ci);
            int par = j & 1;
            if (lane == 0) { fV[par][wid] = wm; fI[par][wid] = wi; }
            __syncthreads();
            unsigned bv = fV[par][0], bp = fI[par][0];
            #pragma unroll
            for (int w2 = 1; w2 < NW; w2++) {
                unsigned v = fV[par][w2], i2 = fI[par][w2];
                if (v > bv || (v == bv && i2 < bp)) { bv = v; bp = i2; }
            }
            float4 pw = comp[bp];
            lx = pw.x; ly = pw.y; lz = pw.z;
            if (tid == 0) g_buf[b][off + j] = __float_as_int(pw.w);
        }
    }
}

// ---- gather output ----
__global__ void k_out(const float* __restrict__ points, float* __restrict__ out) {
    int t = blockIdx.x * blockDim.x + threadIdx.x;
    if (t >= BN * KK) return;
    int b = t / KK, i = t - b * KK;
    int cs[NS];
    int total = g_cnt[b][6];
    #pragma unroll
    for (int s = 0; s < NS; s++) { cs[s] = g_cnt[b][s]; total += cs[s]; }
    if (total < 1) total = 1;
    int st = 0;
    #pragma unroll
    for (int s = 0; s < NS; s++) {
        float q = __fdiv_rn(__fmul_rn((float)cs[s], 2048.0f), (float)total);
        int n = (int)ceilf(q);
        if (n > cs[s]) n = cs[s];
        st += n;
    }
    if (st < 1) st = 1;
    int src = g_buf[b][i % st];
    const float* p = points + ((size_t)b * NP + src) * 3;
    out[3 * t + 0] = p[0];
    out[3 * t + 1] = p[1];
    out[3 * t + 2] = p[2];
}

extern "C" void kernel_launch(void* const* d_in, const int* in_sizes, int n_in,
                              void* d_out, int out_size) {
    const float* points = (const float*)d_in[0];  // [2,65536,3] f32
    const float* rois   = (const float*)d_in[1];  // [2,128,7]  f32
    float* out = (float*)d_out;                   // [2,2048,3] f32

    cudaFuncSetAttribute(k_fps8, cudaFuncAttributeMaxDynamicSharedMemorySize, SMEM_FPS);

    dim3 gc(NP / 256, BN);
    k_classify<<<gc, 256>>>(points, rois);
    k_compact<<<NBS + BN, 1024>>>(points);
    k_fps8<<<NBS, FT, SMEM_FPS>>>();
    k_out<<<(BN * KK + 255) / 256, 256>>>(points, out);
}